// round 15
// baseline (speedup 1.0000x reference)
#include <cuda_runtime.h>
#include <cuda_bf16.h>
#include <math.h>
#include <stdint.h>

// Problem constants
#define Nn    10000
#define Ff    64
#define Uu    128
#define Bb    8
#define Ee    160000
#define Mm    5
#define ROWS  (Bb*Nn)      /* 80000 */
#define K1    (Mm*Ff)      /* 320 */
#define Wd64  512          /* F*B */
#define ZW    2560         /* Z row width = Bb*320 */

// ================= scratch (device globals) =================
__device__ __align__(128) float g_t1  [(size_t)Nn*Wd64];   // S1 x chain / u1
__device__ __align__(128) float g_t3  [(size_t)Nn*Wd64];   // S2 x chain / u2
__device__ __align__(128) float g_Z   [(size_t)Nn*ZW];     // Z[n][b*320 + m*64 + f]
__device__ __align__(128) __nv_bfloat16 g_A64h[(size_t)ROWS*K1];
__device__ __align__(128) __nv_bfloat16 g_A64l[(size_t)ROWS*K1];
__device__ __align__(128) __nv_bfloat16 g_c0h[(size_t)ROWS*Uu];
__device__ __align__(128) __nv_bfloat16 g_c0l[(size_t)ROWS*Uu];
__device__ __align__(128) float g_theta[(size_t)ROWS*Ff];
__device__ __align__(128) __nv_bfloat16 g_Bch[192*K1], g_Bcl[192*K1];
__device__ __align__(128) __nv_bfloat16 g_Bzh[320*Uu], g_Bzl[320*Uu];
__device__ int   g_deg   [2*Nn];
__device__ int   g_rowptr[2*(Nn+1)];   // ABSOLUTE offsets (support2 includes +Ee)
__device__ int   g_pos   [2*Nn];
__device__ int   g_bsum  [64];
__device__ int   g_csr_src[2*Ee];
__device__ float g_csr_w  [2*Ee];
__device__ int   g_csr_eid[2*Ee];

// ================= helpers =================
__device__ __forceinline__ uint32_t smem_u32(const void* p) {
    uint32_t a;
    asm("{ .reg .u64 t; cvta.to.shared.u64 t, %1; cvt.u32.u64 %0, t; }" : "=r"(a) : "l"(p));
    return a;
}
__device__ __forceinline__ void cp16(uint32_t s, const void* g) {
    asm volatile("cp.async.cg.shared.global [%0], [%1], 16;" :: "r"(s), "l"(g));
}
__device__ __forceinline__ void cp_commit() { asm volatile("cp.async.commit_group;"); }
template<int N> __device__ __forceinline__ void cp_wait() {
    asm volatile("cp.async.wait_group %0;" :: "n"(N));
}
__device__ __forceinline__ void mma16816(float* c, const uint32_t* a, const uint32_t* b) {
    asm volatile("mma.sync.aligned.m16n8k16.row.col.f32.bf16.bf16.f32 "
        "{%0,%1,%2,%3}, {%4,%5,%6,%7}, {%8,%9}, {%0,%1,%2,%3};"
        : "+f"(c[0]), "+f"(c[1]), "+f"(c[2]), "+f"(c[3])
        : "r"(a[0]), "r"(a[1]), "r"(a[2]), "r"(a[3]), "r"(b[0]), "r"(b[1]));
}
__device__ __forceinline__ void ldsm4(uint32_t* r, uint32_t addr) {
    asm volatile("ldmatrix.sync.aligned.m8n8.x4.shared.b16 {%0,%1,%2,%3}, [%4];"
        : "=r"(r[0]), "=r"(r[1]), "=r"(r[2]), "=r"(r[3]) : "r"(addr));
}

// vectorized deterministic CSR gather: 4 consecutive floats per thread.
__device__ __forceinline__ float4 gather4(
    const int* __restrict__ rp, int n,
    const int* __restrict__ src, const float* __restrict__ w,
    const float* __restrict__ xin, size_t stride, size_t io)
{
    float4 a = make_float4(0.f, 0.f, 0.f, 0.f);
    int beg = rp[n], end = rp[n + 1];
    int e = beg;
    for (; e + 4 <= end; e += 4) {
        int   s0 = src[e],   s1 = src[e+1], s2 = src[e+2], s3 = src[e+3];
        float w0 = w[e],     w1 = w[e+1],   w2 = w[e+2],   w3 = w[e+3];
        float4 v0 = *(const float4*)(xin + (size_t)s0 * stride + io);
        float4 v1 = *(const float4*)(xin + (size_t)s1 * stride + io);
        float4 v2 = *(const float4*)(xin + (size_t)s2 * stride + io);
        float4 v3 = *(const float4*)(xin + (size_t)s3 * stride + io);
        a.x += w0*v0.x; a.y += w0*v0.y; a.z += w0*v0.z; a.w += w0*v0.w;
        a.x += w1*v1.x; a.y += w1*v1.y; a.z += w1*v1.z; a.w += w1*v1.w;
        a.x += w2*v2.x; a.y += w2*v2.y; a.z += w2*v2.z; a.w += w2*v2.w;
        a.x += w3*v3.x; a.y += w3*v3.y; a.z += w3*v3.z; a.w += w3*v3.w;
    }
    for (; e < end; e++) {
        float wt = w[e];
        float4 v = *(const float4*)(xin + (size_t)src[e] * stride + io);
        a.x += wt*v.x; a.y += wt*v.y; a.z += wt*v.z; a.w += wt*v.w;
    }
    return a;
}

// pack 4 fp32 -> bf16 hi/lo (8B stores)
__device__ __forceinline__ void pack4(__nv_bfloat16* ph, __nv_bfloat16* pl, float4 v) {
    __nv_bfloat162 h01 = __halves2bfloat162(__float2bfloat16(v.x), __float2bfloat16(v.y));
    __nv_bfloat162 h23 = __halves2bfloat162(__float2bfloat16(v.z), __float2bfloat16(v.w));
    __nv_bfloat162 l01 = __halves2bfloat162(
        __float2bfloat16(v.x - __bfloat162float(__low2bfloat16(h01))),
        __float2bfloat16(v.y - __bfloat162float(__high2bfloat16(h01))));
    __nv_bfloat162 l23 = __halves2bfloat162(
        __float2bfloat16(v.z - __bfloat162float(__low2bfloat16(h23))),
        __float2bfloat16(v.w - __bfloat162float(__high2bfloat16(h23))));
    uint2 uh = make_uint2(*(uint32_t*)&h01, *(uint32_t*)&h23);
    uint2 ul = make_uint2(*(uint32_t*)&l01, *(uint32_t*)&l23);
    *(uint2*)ph = uh;
    *(uint2*)pl = ul;
}

// ================= setup: zero degrees + weight prep (merged) =================
__global__ void k_setup(const float* __restrict__ Wl, const float* __restrict__ Wu,
                        const float* __restrict__ Wf) {
    int i = blockIdx.x * blockDim.x + threadIdx.x;
    if (i < 2 * Nn) { g_deg[i] = 0; return; }
    int j = i - 2 * Nn;
    float v; __nv_bfloat16 *ph, *pl; int di;
    if (j < 192 * K1) {
        int n = j / K1, k = j % K1;
        int m = k / 64, f = k % 64;
        v = (n < 64) ? Wl[(f * Mm + m) * 64 + n]
                     : Wu[(f * Mm + m) * 128 + (n - 64)];
        ph = g_Bch; pl = g_Bcl; di = j;
    } else if (j < 192 * K1 + 320 * Uu) {
        int jj = j - 192 * K1;
        int oc = jj / Uu, u = jj % Uu;
        int m = oc / 64, fo = oc % 64;
        if (m == 0) {
            v = Wf[(u * Mm + 0) * 64 + fo] - Wf[(u * Mm + 2) * 64 + fo]
              - Wf[(u * Mm + 4) * 64 + fo];
        } else {
            v = Wf[(u * Mm + m) * 64 + fo];
            if (m == 2 || m == 4) v *= 2.f;
        }
        ph = g_Bzh; pl = g_Bzl; di = jj;
    } else return;
    __nv_bfloat16 h = __float2bfloat16(v);
    ph[di] = h;
    pl[di] = __float2bfloat16(v - __bfloat162float(h));
}

// ================= CSR construction (deterministic) =================
__global__ void k_hist(const int* __restrict__ er, const int* __restrict__ ec) {
    int e = blockIdx.x * blockDim.x + threadIdx.x;
    if (e >= Ee) return;
    atomicAdd(&g_deg[ec[e]], 1);
    atomicAdd(&g_deg[Nn + er[e]], 1);
}
__global__ __launch_bounds__(512) void k_scan1() {
    __shared__ int sh[512];
    int tid = threadIdx.x;
    int i = blockIdx.x * 512 + tid;
    int v = (i < 2 * Nn) ? g_deg[i] : 0;
    sh[tid] = v;
    __syncthreads();
#pragma unroll
    for (int off = 1; off < 512; off <<= 1) {
        int t = (tid >= off) ? sh[tid - off] : 0;
        __syncthreads();
        sh[tid] += t;
        __syncthreads();
    }
    if (i < 2 * Nn) g_pos[i] = sh[tid] - v;
    if (tid == 511) g_bsum[blockIdx.x] = sh[511];
}
__global__ void k_scan3() {
    int i = blockIdx.x * blockDim.x + threadIdx.x;
    if (i >= 2 * Nn) return;
    int blk = i >> 9;
    int c = 0;
    for (int b2 = 0; b2 < blk; b2++) c += g_bsum[b2];
    int val = g_pos[i] + c;
    g_pos[i] = val;
    if (i < Nn) g_rowptr[i] = val;
    else        g_rowptr[(Nn + 1) + (i - Nn)] = val;
    if (i == 0) { g_rowptr[Nn] = Ee; g_rowptr[(Nn + 1) + Nn] = 2 * Ee; }
}
__global__ void k_fill(const int* __restrict__ er, const int* __restrict__ ec,
                       const float* __restrict__ w1, const float* __restrict__ w2) {
    int e = blockIdx.x * blockDim.x + threadIdx.x;
    if (e >= Ee) return;
    {
        int p = atomicAdd(&g_pos[ec[e]], 1);
        g_csr_src[p] = er[e]; g_csr_w[p] = w1[e]; g_csr_eid[p] = e;
    }
    {
        int p = atomicAdd(&g_pos[Nn + er[e]], 1);   // absolute (includes +Ee)
        g_csr_src[p] = ec[e]; g_csr_w[p] = w2[e]; g_csr_eid[p] = e;
    }
}
__global__ void k_sortrows() {
    int idx = blockIdx.x * blockDim.x + threadIdx.x;
    if (idx >= 2 * Nn) return;
    int sup = idx / Nn, n = idx % Nn;
    int beg = g_rowptr[sup * (Nn + 1) + n];
    int end = g_rowptr[sup * (Nn + 1) + n + 1];
    for (int i = beg + 1; i < end; i++) {
        int ke = g_csr_eid[i], ks = g_csr_src[i];
        float kw = g_csr_w[i];
        int j = i - 1;
        while (j >= beg && g_csr_eid[j] > ke) {
            g_csr_eid[j + 1] = g_csr_eid[j];
            g_csr_src[j + 1] = g_csr_src[j];
            g_csr_w  [j + 1] = g_csr_w[j];
            j--;
        }
        g_csr_eid[j + 1] = ke; g_csr_src[j + 1] = ks; g_csr_w[j + 1] = kw;
    }
}

// ================= fused F-width SPMM, per-(node,support) blocks (128 thr) ==========
// grid (Nn, 2): blockIdx.y = support s. y layout: (b*Nn + src)*64 + f.
// PASS 1: s0: t1 = S1 x (pack m=1, also m=0 from y); s1: t3 = S2 x (pack m=3)
// PASS 2: s0: pack m=2 = 2 S1 t1 - x ; s1: pack m=4 = 2 S2 t3 - x
template<int PASS>
__global__ __launch_bounds__(128)
void k_fspmm(const int* __restrict__ rp1, const int* __restrict__ rp2,
             const int* __restrict__ src, const float* __restrict__ w,
             const float* __restrict__ y, float* __restrict__ t1,
             float* __restrict__ t3,
             __nv_bfloat16* __restrict__ Ah, __nv_bfloat16* __restrict__ Al)
{
    int n = blockIdx.x;
    int sup = blockIdx.y;
    int ht = threadIdx.x, o = ht * 4;
    int b = ht >> 4, f = (ht & 15) * 4;
    const int* rp = sup ? rp2 : rp1;
    float4 g;
    if (PASS == 1) {
        size_t io = (size_t)b * Nn * 64 + f;
        g = gather4(rp, n, src, w, y, 64, io);
        float* outn = sup ? t3 : t1;
        *(float4*)(outn + (size_t)n * Wd64 + o) = g;
        if (sup == 0) {   // pack m=0 straight from y
            float4 xv = *(const float4*)(y + ((size_t)b * Nn + n) * 64 + f);
            size_t d0 = ((size_t)b * Nn + n) * K1 + f;
            pack4(Ah + d0, Al + d0, xv);
        }
    } else {
        g = gather4(rp, n, src, w, sup ? t3 : t1, Wd64, o);
        float4 xv = *(const float4*)(y + ((size_t)b * Nn + n) * 64 + f);
        g.x = 2.f*g.x - xv.x; g.y = 2.f*g.y - xv.y;
        g.z = 2.f*g.z - xv.z; g.w = 2.f*g.w - xv.w;
    }
    int m = (PASS == 1) ? (sup ? 3 : 1) : (sup ? 4 : 2);
    size_t dst = ((size_t)b * Nn + n) * K1 + m * 64 + f;
    pack4(Ah + dst, Al + dst, g);
}

// ================= gconv3 pass 1, per-(node,support): u_s = Z(2s+1) + S_s Z(2s+2)' =====
__global__ __launch_bounds__(128)
void k_zu(const int* __restrict__ rp1, const int* __restrict__ rp2,
          const int* __restrict__ src, const float* __restrict__ w,
          const float* __restrict__ Z, float* __restrict__ u1, float* __restrict__ u2)
{
    int n = blockIdx.x;
    int sup = blockIdx.y;
    int ht = threadIdx.x;
    int b = ht >> 4, f = (ht & 15) * 4, o = ht * 4;
    const int* rp = sup ? rp2 : rp1;
    size_t io = (size_t)b * 320 + (sup ? 256 : 128) + f;   // Z4' : Z2'
    float4 g = gather4(rp, n, src, w, Z, ZW, io);
    float4 zl = *(const float4*)(Z + (size_t)n * ZW + b * 320 + (sup ? 192 : 64) + f);
    g.x += zl.x; g.y += zl.y; g.z += zl.z; g.w += zl.w;
    float* outn = sup ? u2 : u1;
    *(float4*)(outn + (size_t)n * Wd64 + o) = g;
}

// ================= gconv3 final: out = -theta * tanh(Z0 + S1 u1 + S2 u2 + b) ==========
__global__ __launch_bounds__(256)
void k_zf(const int* __restrict__ rp1, const int* __restrict__ rp2,
          const int* __restrict__ src, const float* __restrict__ w,
          const float* __restrict__ u1, const float* __restrict__ u2,
          const float* __restrict__ Z,
          const float* __restrict__ theta, const float* __restrict__ b_lat,
          float* __restrict__ out)
{
    __shared__ __align__(16) float sg[1024];
    int n = blockIdx.x, tid = threadIdx.x;
    int half = tid >> 7, ht = tid & 127, o = ht * 4;
    const int* rp = half ? rp2 : rp1;
    const float* xin = half ? u2 : u1;
    float4 g = gather4(rp, n, src, w, xin, Wd64, o);
    *(float4*)(sg + half * 512 + o) = g;
    __syncthreads();
    int o2 = tid * 2;
    int b = o2 >> 6, f = o2 & 63;
    float2 z0 = *(const float2*)(Z + (size_t)n * ZW + b * 320 + f);
    float vx = z0.x + sg[o2]     + sg[512 + o2];
    float vy = z0.y + sg[o2 + 1] + sg[512 + o2 + 1];
    size_t ro = ((size_t)b * Nn + n) * 64 + f;
    float tx = tanhf(vx + __ldg(&b_lat[f]));
    float ty = tanhf(vy + __ldg(&b_lat[f + 1]));
    float2 th = *(const float2*)(theta + ro);
    float2 ov;
    ov.x = -th.x * tx;
    ov.y = -th.y * ty;
    *(float2*)(out + ro) = ov;
}

// ================= bf16-split HMMA GEMM (ldmatrix fragments) =================
// MODE 0 (BN=192, K=K1): col<64 -> theta=sigmoid(.+b_lat); col>=64 -> c0 hi/lo
// MODE 2 (BN=160, K=128): Z[n][b*320 + gcol]
template<int BN, int MODE>
__global__ __launch_bounds__(256, 1)
void k_mma(const __nv_bfloat16* __restrict__ Ahi, const __nv_bfloat16* __restrict__ Alo,
           int K,
           const __nv_bfloat16* __restrict__ Bhi, const __nv_bfloat16* __restrict__ Blo,
           const float* __restrict__ bias_a, const float* __restrict__ bias_b,
           float* __restrict__ theta,
           __nv_bfloat16* __restrict__ c0h, __nv_bfloat16* __restrict__ c0l,
           float* __restrict__ Zout)
{
    constexpr int WN = BN / 2;
    constexpr int NT = WN / 8;
    constexpr int RSTRIDE = 80;
    constexpr int ABYTES = 128 * RSTRIDE;
    constexpr int BBYTES = BN * RSTRIDE;
    constexpr int STAGE = 2 * ABYTES + 2 * BBYTES;

    extern __shared__ __align__(128) char sm[];
    const int tid = threadIdx.x;
    const int lane = tid & 31, wid = tid >> 5;
    const int wm = wid & 3, wn = wid >> 2;
    const size_t rb = (size_t)blockIdx.x * 128;
    const int S = K / 32;
    const uint32_t smbase = smem_u32(sm);

    if (MODE == 2) {
        Bhi += (size_t)blockIdx.y * BN * K;
        Blo += (size_t)blockIdx.y * BN * K;
    }

    float acc[2][NT][4];
#pragma unroll
    for (int a = 0; a < 2; a++)
#pragma unroll
        for (int b = 0; b < NT; b++)
#pragma unroll
            for (int c = 0; c < 4; c++) acc[a][b][c] = 0.f;

    auto load_stage = [&](int kc, int s) {
        uint32_t sa = smbase + s * STAGE;
#pragma unroll
        for (int it = 0; it < 2; it++) {
            int i = tid + it * 256;
            int r = i >> 2, q = i & 3;
            size_t g = (rb + r) * (size_t)K + kc * 32 + q * 8;
            cp16(sa + r * RSTRIDE + q * 16, Ahi + g);
            cp16(sa + ABYTES + r * RSTRIDE + q * 16, Alo + g);
        }
        constexpr int BCH = BN * 4;
        for (int i = tid; i < BCH; i += 256) {
            int r = i >> 2, q = i & 3;
            size_t g = (size_t)r * K + kc * 32 + q * 8;
            cp16(sa + 2 * ABYTES + r * RSTRIDE + q * 16, Bhi + g);
            cp16(sa + 2 * ABYTES + BBYTES + r * RSTRIDE + q * 16, Blo + g);
        }
        cp_commit();
    };

    load_stage(0, 0);

    const int a_row = (lane & 15);
    const int a_kb  = (lane >> 4) * 16;
    const int b_row = ((lane >> 4) << 3) + (lane & 7);
    const int b_kb  = ((lane >> 3) & 1) * 16;

    for (int kc = 0; kc < S; kc++) {
        if (kc + 1 < S) {
            load_stage(kc + 1, (kc + 1) & 1);
            cp_wait<1>();
        } else {
            cp_wait<0>();
        }
        __syncthreads();

        const uint32_t st   = smbase + (kc & 1) * STAGE;
        const uint32_t Ah_s = st;
        const uint32_t Al_s = st + ABYTES;
        const uint32_t Bh_s = st + 2 * ABYTES;
        const uint32_t Bl_s = st + 2 * ABYTES + BBYTES;

#pragma unroll
        for (int k16 = 0; k16 < 2; k16++) {
            const int kb = k16 * 32;
            uint32_t ah[2][4], al[2][4];
#pragma unroll
            for (int mt = 0; mt < 2; mt++) {
                uint32_t ra = (wm * 32 + mt * 16 + a_row) * RSTRIDE + kb + a_kb;
                ldsm4(ah[mt], Ah_s + ra);
                ldsm4(al[mt], Al_s + ra);
            }
#pragma unroll
            for (int ntp = 0; ntp < NT / 2; ntp++) {
                uint32_t rbo = (wn * WN + ntp * 16 + b_row) * RSTRIDE + kb + b_kb;
                uint32_t b4h[4], b4l[4];
                ldsm4(b4h, Bh_s + rbo);
                ldsm4(b4l, Bl_s + rbo);
#pragma unroll
                for (int sub = 0; sub < 2; sub++) {
                    int nt = ntp * 2 + sub;
#pragma unroll
                    for (int mt = 0; mt < 2; mt++) {
                        mma16816(acc[mt][nt], ah[mt], &b4h[sub * 2]);
                        mma16816(acc[mt][nt], al[mt], &b4h[sub * 2]);
                        mma16816(acc[mt][nt], ah[mt], &b4l[sub * 2]);
                    }
                }
            }
        }
        __syncthreads();
    }

    const int r0 = lane >> 2, cq = (lane & 3) * 2;
#pragma unroll
    for (int mt = 0; mt < 2; mt++) {
#pragma unroll
        for (int nt = 0; nt < NT; nt++) {
#pragma unroll
            for (int e = 0; e < 4; e++) {
                int row = (int)rb + wm * 32 + mt * 16 + r0 + ((e >> 1) << 3);
                int col = wn * WN + nt * 8 + cq + (e & 1);
                float v = acc[mt][nt][e];
                if (MODE == 0) {
                    if (col < 64) {
                        theta[(size_t)row * 64 + col] =
                            1.f / (1.f + __expf(-(v + __ldg(&bias_a[col]))));
                    } else {
                        int u = col - 64;
                        float t = tanhf(v + __ldg(&bias_b[u]));
                        __nv_bfloat16 h = __float2bfloat16(t);
                        c0h[(size_t)row * 128 + u] = h;
                        c0l[(size_t)row * 128 + u] =
                            __float2bfloat16(t - __bfloat162float(h));
                    }
                } else {
                    int gcol = blockIdx.y * BN + col;
                    int b = row / Nn, n = row - b * Nn;
                    Zout[(size_t)n * ZW + b * 320 + gcol] = v;
                }
            }
        }
    }
}

// ================= host launch =================
extern "C" void kernel_launch(void* const* d_in, const int* in_sizes, int n_in,
                              void* d_out, int out_size)
{
    (void)in_sizes; (void)n_in; (void)out_size;
    const float* y       = (const float*)d_in[0];
    const float* W_lat   = (const float*)d_in[1];
    const float* b_lat   = (const float*)d_in[2];
    const float* W_units = (const float*)d_in[3];
    const float* b_units = (const float*)d_in[4];
    const float* W_fin   = (const float*)d_in[5];
    const float* s1w     = (const float*)d_in[6];
    const float* s2w     = (const float*)d_in[7];
    const int*   erows   = (const int*)d_in[8];
    const int*   ecols   = (const int*)d_in[9];
    float* out = (float*)d_out;

    void *pt1, *pt3, *pZ, *pth, *prp, *psrc, *pw;
    void *pA64h, *pA64l, *pc0h, *pc0l, *pBch, *pBcl, *pBzh, *pBzl;
    cudaGetSymbolAddress(&pt1, g_t1);
    cudaGetSymbolAddress(&pt3, g_t3);
    cudaGetSymbolAddress(&pZ,  g_Z);
    cudaGetSymbolAddress(&pth, g_theta);
    cudaGetSymbolAddress(&prp, g_rowptr);
    cudaGetSymbolAddress(&psrc, g_csr_src);
    cudaGetSymbolAddress(&pw,  g_csr_w);
    cudaGetSymbolAddress(&pA64h, g_A64h); cudaGetSymbolAddress(&pA64l, g_A64l);
    cudaGetSymbolAddress(&pc0h,  g_c0h);  cudaGetSymbolAddress(&pc0l,  g_c0l);
    cudaGetSymbolAddress(&pBch,  g_Bch);  cudaGetSymbolAddress(&pBcl,  g_Bcl);
    cudaGetSymbolAddress(&pBzh,  g_Bzh);  cudaGetSymbolAddress(&pBzl,  g_Bzl);

    float* t1   = (float*)pt1;
    float* t3   = (float*)pt3;
    float* Z    = (float*)pZ;
    float* th   = (float*)pth;
    int*   rp   = (int*)prp;
    int*   csrc = (int*)psrc;
    float* cw   = (float*)pw;
    __nv_bfloat16 *A64h = (__nv_bfloat16*)pA64h, *A64l = (__nv_bfloat16*)pA64l;
    __nv_bfloat16 *c0h  = (__nv_bfloat16*)pc0h,  *c0l  = (__nv_bfloat16*)pc0l;
    __nv_bfloat16 *Bch  = (__nv_bfloat16*)pBch,  *Bcl  = (__nv_bfloat16*)pBcl;
    __nv_bfloat16 *Bzh  = (__nv_bfloat16*)pBzh,  *Bzl  = (__nv_bfloat16*)pBzl;

    constexpr int SM192 = 2 * (2 * 128 * 80 + 2 * 192 * 80);  // 102400
    constexpr int SM160 = 2 * (2 * 128 * 80 + 2 * 160 * 80);  // 92160
    cudaFuncSetAttribute(k_mma<192, 0>, cudaFuncAttributeMaxDynamicSharedMemorySize, SM192);
    cudaFuncSetAttribute(k_mma<160, 2>, cudaFuncAttributeMaxDynamicSharedMemorySize, SM160);

    const int* rp1 = rp;
    const int* rp2 = rp + (Nn + 1);

    // --- setup (zero deg + weight prep) ---
    int nset = 2 * Nn + 192 * K1 + 320 * Uu;
    k_setup<<<(nset + 255) / 256, 256>>>(W_lat, W_units, W_fin);

    // --- CSR build (deterministic, parallel scan) ---
    k_hist<<<(Ee + 255) / 256, 256>>>(erows, ecols);
    int nb = (2 * Nn + 511) / 512;
    k_scan1<<<nb, 512>>>();
    k_scan3<<<(2 * Nn + 255) / 256, 256>>>();
    k_fill<<<(Ee + 255) / 256, 256>>>(erows, ecols, s1w, s2w);
    k_sortrows<<<(2 * Nn + 255) / 256, 256>>>();

    // --- F-width diffusion (2 passes, per-(node,support) 128-thr blocks) ---
    {
        dim3 g(Nn, 2);
        k_fspmm<1><<<g, 128>>>(rp1, rp2, csrc, cw, y, t1, t3, A64h, A64l);
        k_fspmm<2><<<g, 128>>>(rp1, rp2, csrc, cw, y, t1, t3, A64h, A64l);
    }

    // --- fused gconv1+gconv2: theta + c0 hi/lo ---
    k_mma<192, 0><<<ROWS / 128, 256, SM192>>>(A64h, A64l, K1, Bch, Bcl,
                                              b_lat, b_units, th, c0h, c0l, nullptr);

    // --- Z-GEMM: Z = c0 @ Wz (m0 folded, m2/m4 pre-scaled 2x) ---
    {
        dim3 g(ROWS / 128, 2);
        k_mma<160, 2><<<g, 256, SM160>>>(c0h, c0l, 128, Bzh, Bzl,
                                         nullptr, nullptr, nullptr, nullptr, nullptr, Z);
    }

    // --- gconv3 diffusion in Z-space ---
    {
        dim3 g(Nn, 2);
        k_zu<<<g, 128>>>(rp1, rp2, csrc, cw, Z, t1, t3);
    }
    k_zf<<<Nn, 256>>>(rp1, rp2, csrc, cw, t1, t3, Z, th, b_lat, out);
}

// round 16
// speedup vs baseline: 1.0269x; 1.0269x over previous
#include <cuda_runtime.h>
#include <cuda_bf16.h>
#include <math.h>
#include <stdint.h>

// Problem constants
#define Nn    10000
#define Ff    64
#define Uu    128
#define Bb    8
#define Ee    160000
#define Mm    5
#define ROWS  (Bb*Nn)      /* 80000 */
#define K1    (Mm*Ff)      /* 320 */
#define Wd64  512          /* F*B */
#define ZW    2560         /* Z row width = Bb*320 */

// ================= scratch (device globals) =================
__device__ __align__(128) float g_t1  [(size_t)Nn*Wd64];   // S1 x chain / u1
__device__ __align__(128) float g_t3  [(size_t)Nn*Wd64];   // S2 x chain / u2
__device__ __align__(128) float g_Z   [(size_t)Nn*ZW];     // Z[n][b*320 + m*64 + f]
__device__ __align__(128) __nv_bfloat16 g_A64h[(size_t)ROWS*K1];
__device__ __align__(128) __nv_bfloat16 g_A64l[(size_t)ROWS*K1];
__device__ __align__(128) __nv_bfloat16 g_c0h[(size_t)ROWS*Uu];
__device__ __align__(128) __nv_bfloat16 g_c0l[(size_t)ROWS*Uu];
__device__ __align__(128) float g_theta[(size_t)ROWS*Ff];
__device__ __align__(128) __nv_bfloat16 g_Bch[192*K1], g_Bcl[192*K1]; // [W_lat|W_units]^T
__device__ __align__(128) __nv_bfloat16 g_Bzh[320*Uu], g_Bzl[320*Uu];
__device__ int   g_deg   [2*Nn];
__device__ int   g_rowptr[2*(Nn+1)];   // ABSOLUTE offsets (support2 includes +Ee)
__device__ int   g_pos   [2*Nn];
__device__ int   g_bsum  [64];
__device__ int   g_csr_src[2*Ee];
__device__ float g_csr_w  [2*Ee];
__device__ int   g_csr_eid[2*Ee];

// ================= helpers =================
__device__ __forceinline__ uint32_t smem_u32(const void* p) {
    uint32_t a;
    asm("{ .reg .u64 t; cvta.to.shared.u64 t, %1; cvt.u32.u64 %0, t; }" : "=r"(a) : "l"(p));
    return a;
}
__device__ __forceinline__ void cp16(uint32_t s, const void* g) {
    asm volatile("cp.async.cg.shared.global [%0], [%1], 16;" :: "r"(s), "l"(g));
}
__device__ __forceinline__ void cp_commit() { asm volatile("cp.async.commit_group;"); }
template<int N> __device__ __forceinline__ void cp_wait() {
    asm volatile("cp.async.wait_group %0;" :: "n"(N));
}
__device__ __forceinline__ void mma16816(float* c, const uint32_t* a, const uint32_t* b) {
    asm volatile("mma.sync.aligned.m16n8k16.row.col.f32.bf16.bf16.f32 "
        "{%0,%1,%2,%3}, {%4,%5,%6,%7}, {%8,%9}, {%0,%1,%2,%3};"
        : "+f"(c[0]), "+f"(c[1]), "+f"(c[2]), "+f"(c[3])
        : "r"(a[0]), "r"(a[1]), "r"(a[2]), "r"(a[3]), "r"(b[0]), "r"(b[1]));
}
__device__ __forceinline__ void ldsm4(uint32_t* r, uint32_t addr) {
    asm volatile("ldmatrix.sync.aligned.m8n8.x4.shared.b16 {%0,%1,%2,%3}, [%4];"
        : "=r"(r[0]), "=r"(r[1]), "=r"(r[2]), "=r"(r[3]) : "r"(addr));
}

// vectorized deterministic CSR gather: 4 consecutive floats per thread.
__device__ __forceinline__ float4 gather4(
    const int* __restrict__ rp, int n,
    const int* __restrict__ src, const float* __restrict__ w,
    const float* __restrict__ xin, size_t stride, size_t io)
{
    float4 a = make_float4(0.f, 0.f, 0.f, 0.f);
    int beg = rp[n], end = rp[n + 1];
    int e = beg;
    for (; e + 4 <= end; e += 4) {
        int   s0 = src[e],   s1 = src[e+1], s2 = src[e+2], s3 = src[e+3];
        float w0 = w[e],     w1 = w[e+1],   w2 = w[e+2],   w3 = w[e+3];
        float4 v0 = *(const float4*)(xin + (size_t)s0 * stride + io);
        float4 v1 = *(const float4*)(xin + (size_t)s1 * stride + io);
        float4 v2 = *(const float4*)(xin + (size_t)s2 * stride + io);
        float4 v3 = *(const float4*)(xin + (size_t)s3 * stride + io);
        a.x += w0*v0.x; a.y += w0*v0.y; a.z += w0*v0.z; a.w += w0*v0.w;
        a.x += w1*v1.x; a.y += w1*v1.y; a.z += w1*v1.z; a.w += w1*v1.w;
        a.x += w2*v2.x; a.y += w2*v2.y; a.z += w2*v2.z; a.w += w2*v2.w;
        a.x += w3*v3.x; a.y += w3*v3.y; a.z += w3*v3.z; a.w += w3*v3.w;
    }
    for (; e < end; e++) {
        float wt = w[e];
        float4 v = *(const float4*)(xin + (size_t)src[e] * stride + io);
        a.x += wt*v.x; a.y += wt*v.y; a.z += wt*v.z; a.w += wt*v.w;
    }
    return a;
}

// pack 4 fp32 -> bf16 hi/lo (8B stores)
__device__ __forceinline__ void pack4(__nv_bfloat16* ph, __nv_bfloat16* pl, float4 v) {
    __nv_bfloat162 h01 = __halves2bfloat162(__float2bfloat16(v.x), __float2bfloat16(v.y));
    __nv_bfloat162 h23 = __halves2bfloat162(__float2bfloat16(v.z), __float2bfloat16(v.w));
    __nv_bfloat162 l01 = __halves2bfloat162(
        __float2bfloat16(v.x - __bfloat162float(__low2bfloat16(h01))),
        __float2bfloat16(v.y - __bfloat162float(__high2bfloat16(h01))));
    __nv_bfloat162 l23 = __halves2bfloat162(
        __float2bfloat16(v.z - __bfloat162float(__low2bfloat16(h23))),
        __float2bfloat16(v.w - __bfloat162float(__high2bfloat16(h23))));
    uint2 uh = make_uint2(*(uint32_t*)&h01, *(uint32_t*)&h23);
    uint2 ul = make_uint2(*(uint32_t*)&l01, *(uint32_t*)&l23);
    *(uint2*)ph = uh;
    *(uint2*)pl = ul;
}

// ================= setup: zero degrees + weight prep (merged) =================
__global__ void k_setup(const float* __restrict__ Wl, const float* __restrict__ Wu,
                        const float* __restrict__ Wf) {
    int i = blockIdx.x * blockDim.x + threadIdx.x;
    if (i < 2 * Nn) { g_deg[i] = 0; return; }
    int j = i - 2 * Nn;
    float v; __nv_bfloat16 *ph, *pl; int di;
    if (j < 192 * K1) {
        int n = j / K1, k = j % K1;
        int m = k / 64, f = k % 64;
        v = (n < 64) ? Wl[(f * Mm + m) * 64 + n]
                     : Wu[(f * Mm + m) * 128 + (n - 64)];
        ph = g_Bch; pl = g_Bcl; di = j;
    } else if (j < 192 * K1 + 320 * Uu) {
        int jj = j - 192 * K1;
        int oc = jj / Uu, u = jj % Uu;
        int m = oc / 64, fo = oc % 64;
        if (m == 0) {
            v = Wf[(u * Mm + 0) * 64 + fo] - Wf[(u * Mm + 2) * 64 + fo]
              - Wf[(u * Mm + 4) * 64 + fo];
        } else {
            v = Wf[(u * Mm + m) * 64 + fo];
            if (m == 2 || m == 4) v *= 2.f;
        }
        ph = g_Bzh; pl = g_Bzl; di = jj;
    } else return;
    __nv_bfloat16 h = __float2bfloat16(v);
    ph[di] = h;
    pl[di] = __float2bfloat16(v - __bfloat162float(h));
}

// ================= CSR construction (deterministic) =================
__global__ void k_hist(const int* __restrict__ er, const int* __restrict__ ec) {
    int e = blockIdx.x * blockDim.x + threadIdx.x;
    if (e >= Ee) return;
    atomicAdd(&g_deg[ec[e]], 1);
    atomicAdd(&g_deg[Nn + er[e]], 1);
}
__global__ __launch_bounds__(512) void k_scan1() {
    __shared__ int sh[512];
    int tid = threadIdx.x;
    int i = blockIdx.x * 512 + tid;
    int v = (i < 2 * Nn) ? g_deg[i] : 0;
    sh[tid] = v;
    __syncthreads();
#pragma unroll
    for (int off = 1; off < 512; off <<= 1) {
        int t = (tid >= off) ? sh[tid - off] : 0;
        __syncthreads();
        sh[tid] += t;
        __syncthreads();
    }
    if (i < 2 * Nn) g_pos[i] = sh[tid] - v;
    if (tid == 511) g_bsum[blockIdx.x] = sh[511];
}
__global__ void k_scan3() {
    int i = blockIdx.x * blockDim.x + threadIdx.x;
    if (i >= 2 * Nn) return;
    int blk = i >> 9;
    int c = 0;
    for (int b2 = 0; b2 < blk; b2++) c += g_bsum[b2];
    int val = g_pos[i] + c;
    g_pos[i] = val;
    if (i < Nn) g_rowptr[i] = val;
    else        g_rowptr[(Nn + 1) + (i - Nn)] = val;
    if (i == 0) { g_rowptr[Nn] = Ee; g_rowptr[(Nn + 1) + Nn] = 2 * Ee; }
}
__global__ void k_fill(const int* __restrict__ er, const int* __restrict__ ec,
                       const float* __restrict__ w1, const float* __restrict__ w2) {
    int e = blockIdx.x * blockDim.x + threadIdx.x;
    if (e >= Ee) return;
    {
        int p = atomicAdd(&g_pos[ec[e]], 1);
        g_csr_src[p] = er[e]; g_csr_w[p] = w1[e]; g_csr_eid[p] = e;
    }
    {
        int p = atomicAdd(&g_pos[Nn + er[e]], 1);   // absolute (includes +Ee)
        g_csr_src[p] = ec[e]; g_csr_w[p] = w2[e]; g_csr_eid[p] = e;
    }
}
__global__ void k_sortrows() {
    int idx = blockIdx.x * blockDim.x + threadIdx.x;
    if (idx >= 2 * Nn) return;
    int sup = idx / Nn, n = idx % Nn;
    int beg = g_rowptr[sup * (Nn + 1) + n];
    int end = g_rowptr[sup * (Nn + 1) + n + 1];
    for (int i = beg + 1; i < end; i++) {
        int ke = g_csr_eid[i], ks = g_csr_src[i];
        float kw = g_csr_w[i];
        int j = i - 1;
        while (j >= beg && g_csr_eid[j] > ke) {
            g_csr_eid[j + 1] = g_csr_eid[j];
            g_csr_src[j + 1] = g_csr_src[j];
            g_csr_w  [j + 1] = g_csr_w[j];
            j--;
        }
        g_csr_eid[j + 1] = ke; g_csr_src[j + 1] = ks; g_csr_w[j + 1] = kw;
    }
}

// ================= fused F-width SPMM, per-(node,support) blocks (128 thr) ==========
template<int PASS>
__global__ __launch_bounds__(128)
void k_fspmm(const int* __restrict__ rp1, const int* __restrict__ rp2,
             const int* __restrict__ src, const float* __restrict__ w,
             const float* __restrict__ y, float* __restrict__ t1,
             float* __restrict__ t3,
             __nv_bfloat16* __restrict__ Ah, __nv_bfloat16* __restrict__ Al)
{
    int n = blockIdx.x;
    int sup = blockIdx.y;
    int ht = threadIdx.x, o = ht * 4;
    int b = ht >> 4, f = (ht & 15) * 4;
    const int* rp = sup ? rp2 : rp1;
    float4 g;
    if (PASS == 1) {
        size_t io = (size_t)b * Nn * 64 + f;
        g = gather4(rp, n, src, w, y, 64, io);
        float* outn = sup ? t3 : t1;
        *(float4*)(outn + (size_t)n * Wd64 + o) = g;
        if (sup == 0) {   // pack m=0 straight from y
            float4 xv = *(const float4*)(y + ((size_t)b * Nn + n) * 64 + f);
            size_t d0 = ((size_t)b * Nn + n) * K1 + f;
            pack4(Ah + d0, Al + d0, xv);
        }
    } else {
        g = gather4(rp, n, src, w, sup ? t3 : t1, Wd64, o);
        float4 xv = *(const float4*)(y + ((size_t)b * Nn + n) * 64 + f);
        g.x = 2.f*g.x - xv.x; g.y = 2.f*g.y - xv.y;
        g.z = 2.f*g.z - xv.z; g.w = 2.f*g.w - xv.w;
    }
    int m = (PASS == 1) ? (sup ? 3 : 1) : (sup ? 4 : 2);
    size_t dst = ((size_t)b * Nn + n) * K1 + m * 64 + f;
    pack4(Ah + dst, Al + dst, g);
}

// ================= gconv3 pass 1, per-(node,support) =================
__global__ __launch_bounds__(128)
void k_zu(const int* __restrict__ rp1, const int* __restrict__ rp2,
          const int* __restrict__ src, const float* __restrict__ w,
          const float* __restrict__ Z, float* __restrict__ u1, float* __restrict__ u2)
{
    int n = blockIdx.x;
    int sup = blockIdx.y;
    int ht = threadIdx.x;
    int b = ht >> 4, f = (ht & 15) * 4, o = ht * 4;
    const int* rp = sup ? rp2 : rp1;
    size_t io = (size_t)b * 320 + (sup ? 256 : 128) + f;   // Z4' : Z2'
    float4 g = gather4(rp, n, src, w, Z, ZW, io);
    float4 zl = *(const float4*)(Z + (size_t)n * ZW + b * 320 + (sup ? 192 : 64) + f);
    g.x += zl.x; g.y += zl.y; g.z += zl.z; g.w += zl.w;
    float* outn = sup ? u2 : u1;
    *(float4*)(outn + (size_t)n * Wd64 + o) = g;
}

// ================= gconv3 final: out = -theta * tanh(Z0 + S1 u1 + S2 u2 + b) ==========
__global__ __launch_bounds__(256)
void k_zf(const int* __restrict__ rp1, const int* __restrict__ rp2,
          const int* __restrict__ src, const float* __restrict__ w,
          const float* __restrict__ u1, const float* __restrict__ u2,
          const float* __restrict__ Z,
          const float* __restrict__ theta, const float* __restrict__ b_lat,
          float* __restrict__ out)
{
    __shared__ __align__(16) float sg[1024];
    int n = blockIdx.x, tid = threadIdx.x;
    int half = tid >> 7, ht = tid & 127, o = ht * 4;
    const int* rp = half ? rp2 : rp1;
    const float* xin = half ? u2 : u1;
    float4 g = gather4(rp, n, src, w, xin, Wd64, o);
    *(float4*)(sg + half * 512 + o) = g;
    __syncthreads();
    int o2 = tid * 2;
    int b = o2 >> 6, f = o2 & 63;
    float2 z0 = *(const float2*)(Z + (size_t)n * ZW + b * 320 + f);
    float vx = z0.x + sg[o2]     + sg[512 + o2];
    float vy = z0.y + sg[o2 + 1] + sg[512 + o2 + 1];
    size_t ro = ((size_t)b * Nn + n) * 64 + f;
    float tx = tanhf(vx + __ldg(&b_lat[f]));
    float ty = tanhf(vy + __ldg(&b_lat[f + 1]));
    float2 th = *(const float2*)(theta + ro);
    float2 ov;
    ov.x = -th.x * tx;
    ov.y = -th.y * ty;
    *(float2*)(out + ro) = ov;
}

// ================= bf16-split HMMA GEMM (ldmatrix fragments) =================
// MODE 0 (BN=64,  K=K1): theta = sigmoid(. + b_lat)          [side stream]
// MODE 1 (BN=128, K=K1): c0 = tanh(. + b_units) hi/lo        [critical path]
// MODE 2 (BN=160, K=128): Z[n][b*320 + gcol]
template<int BN, int MODE>
__global__ __launch_bounds__(256, 1)
void k_mma(const __nv_bfloat16* __restrict__ Ahi, const __nv_bfloat16* __restrict__ Alo,
           int K,
           const __nv_bfloat16* __restrict__ Bhi, const __nv_bfloat16* __restrict__ Blo,
           const float* __restrict__ bias_a, const float* __restrict__ bias_b,
           float* __restrict__ theta,
           __nv_bfloat16* __restrict__ c0h, __nv_bfloat16* __restrict__ c0l,
           float* __restrict__ Zout)
{
    constexpr int WN = BN / 2;
    constexpr int NT = WN / 8;
    constexpr int RSTRIDE = 80;
    constexpr int ABYTES = 128 * RSTRIDE;
    constexpr int BBYTES = BN * RSTRIDE;
    constexpr int STAGE = 2 * ABYTES + 2 * BBYTES;

    extern __shared__ __align__(128) char sm[];
    const int tid = threadIdx.x;
    const int lane = tid & 31, wid = tid >> 5;
    const int wm = wid & 3, wn = wid >> 2;
    const size_t rb = (size_t)blockIdx.x * 128;
    const int S = K / 32;
    const uint32_t smbase = smem_u32(sm);

    if (MODE == 2) {
        Bhi += (size_t)blockIdx.y * BN * K;
        Blo += (size_t)blockIdx.y * BN * K;
    }

    float acc[2][NT][4];
#pragma unroll
    for (int a = 0; a < 2; a++)
#pragma unroll
        for (int b = 0; b < NT; b++)
#pragma unroll
            for (int c = 0; c < 4; c++) acc[a][b][c] = 0.f;

    auto load_stage = [&](int kc, int s) {
        uint32_t sa = smbase + s * STAGE;
#pragma unroll
        for (int it = 0; it < 2; it++) {
            int i = tid + it * 256;
            int r = i >> 2, q = i & 3;
            size_t g = (rb + r) * (size_t)K + kc * 32 + q * 8;
            cp16(sa + r * RSTRIDE + q * 16, Ahi + g);
            cp16(sa + ABYTES + r * RSTRIDE + q * 16, Alo + g);
        }
        constexpr int BCH = BN * 4;
        for (int i = tid; i < BCH; i += 256) {
            int r = i >> 2, q = i & 3;
            size_t g = (size_t)r * K + kc * 32 + q * 8;
            cp16(sa + 2 * ABYTES + r * RSTRIDE + q * 16, Bhi + g);
            cp16(sa + 2 * ABYTES + BBYTES + r * RSTRIDE + q * 16, Blo + g);
        }
        cp_commit();
    };

    load_stage(0, 0);

    const int a_row = (lane & 15);
    const int a_kb  = (lane >> 4) * 16;
    const int b_row = ((lane >> 4) << 3) + (lane & 7);
    const int b_kb  = ((lane >> 3) & 1) * 16;

    for (int kc = 0; kc < S; kc++) {
        if (kc + 1 < S) {
            load_stage(kc + 1, (kc + 1) & 1);
            cp_wait<1>();
        } else {
            cp_wait<0>();
        }
        __syncthreads();

        const uint32_t st   = smbase + (kc & 1) * STAGE;
        const uint32_t Ah_s = st;
        const uint32_t Al_s = st + ABYTES;
        const uint32_t Bh_s = st + 2 * ABYTES;
        const uint32_t Bl_s = st + 2 * ABYTES + BBYTES;

#pragma unroll
        for (int k16 = 0; k16 < 2; k16++) {
            const int kb = k16 * 32;
            uint32_t ah[2][4], al[2][4];
#pragma unroll
            for (int mt = 0; mt < 2; mt++) {
                uint32_t ra = (wm * 32 + mt * 16 + a_row) * RSTRIDE + kb + a_kb;
                ldsm4(ah[mt], Ah_s + ra);
                ldsm4(al[mt], Al_s + ra);
            }
#pragma unroll
            for (int ntp = 0; ntp < NT / 2; ntp++) {
                uint32_t rbo = (wn * WN + ntp * 16 + b_row) * RSTRIDE + kb + b_kb;
                uint32_t b4h[4], b4l[4];
                ldsm4(b4h, Bh_s + rbo);
                ldsm4(b4l, Bl_s + rbo);
#pragma unroll
                for (int sub = 0; sub < 2; sub++) {
                    int nt = ntp * 2 + sub;
#pragma unroll
                    for (int mt = 0; mt < 2; mt++) {
                        mma16816(acc[mt][nt], ah[mt], &b4h[sub * 2]);
                        mma16816(acc[mt][nt], al[mt], &b4h[sub * 2]);
                        mma16816(acc[mt][nt], ah[mt], &b4l[sub * 2]);
                    }
                }
            }
        }
        __syncthreads();
    }

    const int r0 = lane >> 2, cq = (lane & 3) * 2;
#pragma unroll
    for (int mt = 0; mt < 2; mt++) {
#pragma unroll
        for (int nt = 0; nt < NT; nt++) {
#pragma unroll
            for (int e = 0; e < 4; e++) {
                int row = (int)rb + wm * 32 + mt * 16 + r0 + ((e >> 1) << 3);
                int col = wn * WN + nt * 8 + cq + (e & 1);
                float v = acc[mt][nt][e];
                if (MODE == 0) {
                    theta[(size_t)row * 64 + col] =
                        1.f / (1.f + __expf(-(v + __ldg(&bias_a[col]))));
                } else if (MODE == 1) {
                    float t = tanhf(v + __ldg(&bias_b[col]));
                    __nv_bfloat16 h = __float2bfloat16(t);
                    c0h[(size_t)row * 128 + col] = h;
                    c0l[(size_t)row * 128 + col] =
                        __float2bfloat16(t - __bfloat162float(h));
                } else {
                    int gcol = blockIdx.y * BN + col;
                    int b = row / Nn, n = row - b * Nn;
                    Zout[(size_t)n * ZW + b * 320 + gcol] = v;
                }
            }
        }
    }
}

// ================= host launch =================
extern "C" void kernel_launch(void* const* d_in, const int* in_sizes, int n_in,
                              void* d_out, int out_size)
{
    (void)in_sizes; (void)n_in; (void)out_size;
    const float* y       = (const float*)d_in[0];
    const float* W_lat   = (const float*)d_in[1];
    const float* b_lat   = (const float*)d_in[2];
    const float* W_units = (const float*)d_in[3];
    const float* b_units = (const float*)d_in[4];
    const float* W_fin   = (const float*)d_in[5];
    const float* s1w     = (const float*)d_in[6];
    const float* s2w     = (const float*)d_in[7];
    const int*   erows   = (const int*)d_in[8];
    const int*   ecols   = (const int*)d_in[9];
    float* out = (float*)d_out;

    void *pt1, *pt3, *pZ, *pth, *prp, *psrc, *pw;
    void *pA64h, *pA64l, *pc0h, *pc0l, *pBch, *pBcl, *pBzh, *pBzl;
    cudaGetSymbolAddress(&pt1, g_t1);
    cudaGetSymbolAddress(&pt3, g_t3);
    cudaGetSymbolAddress(&pZ,  g_Z);
    cudaGetSymbolAddress(&pth, g_theta);
    cudaGetSymbolAddress(&prp, g_rowptr);
    cudaGetSymbolAddress(&psrc, g_csr_src);
    cudaGetSymbolAddress(&pw,  g_csr_w);
    cudaGetSymbolAddress(&pA64h, g_A64h); cudaGetSymbolAddress(&pA64l, g_A64l);
    cudaGetSymbolAddress(&pc0h,  g_c0h);  cudaGetSymbolAddress(&pc0l,  g_c0l);
    cudaGetSymbolAddress(&pBch,  g_Bch);  cudaGetSymbolAddress(&pBcl,  g_Bcl);
    cudaGetSymbolAddress(&pBzh,  g_Bzh);  cudaGetSymbolAddress(&pBzl,  g_Bzl);

    float* t1   = (float*)pt1;
    float* t3   = (float*)pt3;
    float* Z    = (float*)pZ;
    float* th   = (float*)pth;
    int*   rp   = (int*)prp;
    int*   csrc = (int*)psrc;
    float* cw   = (float*)pw;
    __nv_bfloat16 *A64h = (__nv_bfloat16*)pA64h, *A64l = (__nv_bfloat16*)pA64l;
    __nv_bfloat16 *c0h  = (__nv_bfloat16*)pc0h,  *c0l  = (__nv_bfloat16*)pc0l;
    __nv_bfloat16 *Bch  = (__nv_bfloat16*)pBch,  *Bcl  = (__nv_bfloat16*)pBcl;
    __nv_bfloat16 *Bzh  = (__nv_bfloat16*)pBzh,  *Bzl  = (__nv_bfloat16*)pBzl;

    constexpr int SM64  = 2 * (2 * 128 * 80 + 2 * 64 * 80);   // 61440
    constexpr int SM128 = 2 * (2 * 128 * 80 + 2 * 128 * 80);  // 81920
    constexpr int SM160 = 2 * (2 * 128 * 80 + 2 * 160 * 80);  // 92160
    cudaFuncSetAttribute(k_mma<64, 0>,  cudaFuncAttributeMaxDynamicSharedMemorySize, SM64);
    cudaFuncSetAttribute(k_mma<128, 1>, cudaFuncAttributeMaxDynamicSharedMemorySize, SM128);
    cudaFuncSetAttribute(k_mma<160, 2>, cudaFuncAttributeMaxDynamicSharedMemorySize, SM160);

    const int* rp1 = rp;
    const int* rp2 = rp + (Nn + 1);

    // side stream + fork/join events (created per call; kernel_launch runs twice,
    // so the leaked handles are bounded and no device memory is allocated)
    cudaStream_t s2;
    cudaEvent_t eFork, eJoin;
    cudaStreamCreateWithFlags(&s2, cudaStreamNonBlocking);
    cudaEventCreateWithFlags(&eFork, cudaEventDisableTiming);
    cudaEventCreateWithFlags(&eJoin, cudaEventDisableTiming);

    // --- setup (zero deg + weight prep) ---
    int nset = 2 * Nn + 192 * K1 + 320 * Uu;
    k_setup<<<(nset + 255) / 256, 256>>>(W_lat, W_units, W_fin);

    // --- CSR build (deterministic, parallel scan) ---
    k_hist<<<(Ee + 255) / 256, 256>>>(erows, ecols);
    int nb = (2 * Nn + 511) / 512;
    k_scan1<<<nb, 512>>>();
    k_scan3<<<(2 * Nn + 255) / 256, 256>>>();
    k_fill<<<(Ee + 255) / 256, 256>>>(erows, ecols, s1w, s2w);
    k_sortrows<<<(2 * Nn + 255) / 256, 256>>>();

    // --- F-width diffusion (2 passes, per-(node,support) 128-thr blocks) ---
    {
        dim3 g(Nn, 2);
        k_fspmm<1><<<g, 128>>>(rp1, rp2, csrc, cw, y, t1, t3, A64h, A64l);
        k_fspmm<2><<<g, 128>>>(rp1, rp2, csrc, cw, y, t1, t3, A64h, A64l);
    }

    // --- fork: theta GEMM on side stream (needed only by k_zf) ---
    cudaEventRecord(eFork, 0);
    cudaStreamWaitEvent(s2, eFork, 0);
    k_mma<64, 0><<<ROWS / 128, 256, SM64, s2>>>(A64h, A64l, K1, Bch, Bcl,
                                                b_lat, nullptr, th,
                                                nullptr, nullptr, nullptr);
    cudaEventRecord(eJoin, s2);

    // --- critical path: c0 GEMM ---
    k_mma<128, 1><<<ROWS / 128, 256, SM128>>>(A64h + 0, A64l + 0, K1,
                                              Bch + (size_t)64 * K1, Bcl + (size_t)64 * K1,
                                              nullptr, b_units, nullptr,
                                              c0h, c0l, nullptr);

    // --- Z-GEMM: Z = c0 @ Wz (m0 folded, m2/m4 pre-scaled 2x) ---
    {
        dim3 g(ROWS / 128, 2);
        k_mma<160, 2><<<g, 256, SM160>>>(c0h, c0l, 128, Bzh, Bzl,
                                         nullptr, nullptr, nullptr, nullptr, nullptr, Z);
    }

    // --- gconv3 diffusion in Z-space ---
    {
        dim3 g(Nn, 2);
        k_zu<<<g, 128>>>(rp1, rp2, csrc, cw, Z, t1, t3);
    }

    // --- join: theta must be ready before the final fused kernel ---
    cudaStreamWaitEvent(0, eJoin, 0);
    k_zf<<<Nn, 256>>>(rp1, rp2, csrc, cw, t1, t3, Z, th, b_lat, out);
}